// round 4
// baseline (speedup 1.0000x reference)
#include <cuda_runtime.h>
#include <math.h>

#define B_DIM 64
#define T_DIM 1000
#define P_ORD 10
#define NFRAMES (B_DIM * T_DIM)
#define PI_D 3.14159265358979323846

// Constant 11x11 map (double): r = M * c  (c = autocorrelation of predictor poly A)
// Folds:  S[k] = |rfft(A,512)[k]|^2 over 116 bins,  r = irfft(S, 230)[0:11]
__device__ double d_M[121];
__device__ float d_x0[20];

__global__ void init_consts_kernel() {
    int tid = threadIdx.x;
    if (tid < 121) {
        int j = tid / 11, d = tid % 11;
        double s = (d == 0) ? 1.0 : 2.0;                    // k = 0 bin
        for (int k = 1; k <= 114; k++) {
            double gd = (d == 0) ? 1.0 : 2.0 * cos(2.0 * PI_D * (double)k * (double)d / 512.0);
            s += 2.0 * gd * cos(2.0 * PI_D * (double)k * (double)j / 230.0);
        }
        double g115 = (d == 0) ? 1.0 : 2.0 * cos(2.0 * PI_D * 115.0 * (double)d / 512.0);
        s += ((j & 1) ? -1.0 : 1.0) * g115;                 // k = 115 Nyquist
        d_M[tid] = s / 230.0;
    }
    if (tid == 121) {
        double cr = 1.0, ci = 0.0;
        for (int p = 0; p < 10; p++) {
            double nr = cr * 0.4 - ci * 0.9;
            double ni = cr * 0.9 + ci * 0.4;
            cr = nr; ci = ni;
            d_x0[p]      = (float)nr;
            d_x0[10 + p] = (float)ni;
        }
    }
}

// Complex division matching XLA's lowering: Smith's algorithm (ratio form,
// branch on |c| >= |d|) with __divsc3-style NaN recovery. All ops IEEE rn,
// no FMA contraction.
__device__ __forceinline__ void cdivf(float a, float b, float c, float d,
                                      float& outr, float& outi) {
    float re, im;
    if (fabsf(c) >= fabsf(d)) {
        float r     = __fdiv_rn(d, c);
        float denom = __fadd_rn(c, __fmul_rn(d, r));
        re = __fdiv_rn(__fadd_rn(a, __fmul_rn(b, r)), denom);
        im = __fdiv_rn(__fsub_rn(b, __fmul_rn(a, r)), denom);
    } else {
        float r     = __fdiv_rn(c, d);
        float denom = __fadd_rn(__fmul_rn(c, r), d);
        re = __fdiv_rn(__fadd_rn(__fmul_rn(a, r), b), denom);
        im = __fdiv_rn(__fsub_rn(__fmul_rn(b, r), a), denom);
    }
    if (isnan(re) && isnan(im)) {
        if ((c == 0.0f && d == 0.0f) && (!isnan(a) || !isnan(b))) {
            re = copysignf(INFINITY, c) * a;
            im = copysignf(INFINITY, c) * b;
        } else if ((isinf(a) || isinf(b)) && isfinite(c) && isfinite(d)) {
            float aa = copysignf(isinf(a) ? 1.0f : 0.0f, a);
            float bb = copysignf(isinf(b) ? 1.0f : 0.0f, b);
            re = INFINITY * __fadd_rn(__fmul_rn(aa, c), __fmul_rn(bb, d));
            im = INFINITY * __fsub_rn(__fmul_rn(bb, c), __fmul_rn(aa, d));
        } else if ((isinf(c) || isinf(d)) && isfinite(a) && isfinite(b)) {
            float cc = copysignf(isinf(c) ? 1.0f : 0.0f, c);
            float dd = copysignf(isinf(d) ? 1.0f : 0.0f, d);
            re = 0.0f * __fadd_rn(__fmul_rn(a, cc), __fmul_rn(b, dd));
            im = 0.0f * __fsub_rn(__fmul_rn(b, cc), __fmul_rn(a, dd));
        }
    }
    outr = re; outi = im;
}

__global__ void __launch_bounds__(128)
formant_kernel(const float* __restrict__ in, float* __restrict__ out) {
    __shared__ double sM[121];
    __shared__ float sX0[20];
    if (threadIdx.x < 121) sM[threadIdx.x] = d_M[threadIdx.x];
    if (threadIdx.x < 20)  sX0[threadIdx.x] = d_x0[threadIdx.x];
    __syncthreads();

    int idx = blockIdx.x * blockDim.x + threadIdx.x;
    if (idx >= NFRAMES) return;
    int b = idx / T_DIM;
    int t = idx - b * T_DIM;
    const float* base = in + (size_t)b * (P_ORD * T_DIM) + t;

    // ======== FRONT-END IN DOUBLE (pc = exact math; closest to ref's pc) ========
    double A[11];
    A[0] = 1.0;
    {
        double a[10];
        a[0] = (double)base[0];
#pragma unroll
        for (int p = 1; p < 10; p++) {
            double k = (double)base[p * T_DIM];
            double na[10];
#pragma unroll
            for (int i = 0; i < p; i++) na[i] = a[i] + k * a[p - 1 - i];
#pragma unroll
            for (int i = 0; i < p; i++) a[i] = na[i];
            a[p] = k;
        }
#pragma unroll
        for (int i = 0; i < 10; i++) A[i + 1] = a[i];
    }

    double c[11];
#pragma unroll
    for (int d = 0; d < 11; d++) {
        double s = 0.0;
#pragma unroll
        for (int n = 0; n < 11 - d; n++) s = fma(A[n], A[n + d], s);
        c[d] = s;
    }

    double r[11];
#pragma unroll
    for (int j = 0; j < 11; j++) {
        double s = 0.0;
#pragma unroll
        for (int d = 0; d < 11; d++) s = fma(sM[j * 11 + d], c[d], s);
        r[j] = s;
    }

    float pc[11];
    pc[0] = 1.0f;
    {
        double a[10];
        double k0 = -r[1] / r[0];
        a[0] = k0;
        double err = r[0] * (1.0 - k0 * k0);
#pragma unroll
        for (int m = 1; m < 10; m++) {
            double acc = r[m + 1];
#pragma unroll
            for (int i = 0; i < m; i++) acc = fma(a[i], r[m - i], acc);
            double k = -acc / err;
            double na[10];
#pragma unroll
            for (int i = 0; i < m; i++) na[i] = a[i] + k * a[m - 1 - i];
#pragma unroll
            for (int i = 0; i < m; i++) a[i] = na[i];
            a[m] = k;
            err *= (1.0 - k * k);
        }
#pragma unroll
        for (int i = 0; i < 10; i++) pc[i + 1] = (float)a[i];
    }

    // ======== DURAND-KERNER, fp32, XLA-faithful arithmetic ========
    //  - complex mul: naive (ac-bd, ad+bc), no FMA contraction
    //  - complex div: Smith + NaN recovery (cdivf)
    float xr[10], xi[10];
#pragma unroll
    for (int i = 0; i < 10; i++) { xr[i] = sX0[i]; xi[i] = sX0[10 + i]; }

#pragma unroll 1
    for (int it = 0; it < 30; it++) {
        float nxr[10], nxi[10];
#pragma unroll
        for (int i = 0; i < 10; i++) {
            // Horner polyval at x_i (sequential, unfused)
            float yr = pc[0], yi = 0.f;
#pragma unroll
            for (int m = 1; m <= 10; m++) {
                float tr = __fadd_rn(__fsub_rn(__fmul_rn(yr, xr[i]),
                                               __fmul_rn(yi, xi[i])), pc[m]);
                float ti = __fadd_rn(__fmul_rn(yr, xi[i]),
                                     __fmul_rn(yi, xr[i]));
                yr = tr; yi = ti;
            }
            // prod_j (x_i - x_j + eye_ij), sequential j = 0..9 (j==i factor == 1)
            float dr = 1.f, di = 0.f;
#pragma unroll
            for (int j = 0; j < 10; j++) {
                float er = __fadd_rn(__fsub_rn(xr[i], xr[j]), (i == j) ? 1.f : 0.f);
                float ei = __fsub_rn(xi[i], xi[j]);
                float tr = __fsub_rn(__fmul_rn(dr, er), __fmul_rn(di, ei));
                float ti = __fadd_rn(__fmul_rn(dr, ei), __fmul_rn(di, er));
                dr = tr; di = ti;
            }
            dr = __fadd_rn(dr, 1e-12f);
            float qr, qi;
            cdivf(yr, yi, dr, di, qr, qi);
            nxr[i] = __fsub_rn(xr[i], qr);
            nxi[i] = __fsub_rn(xi[i], qi);
        }
#pragma unroll
        for (int i = 0; i < 10; i++) { xr[i] = nxr[i]; xi[i] = nxi[i]; }
    }

    // ---- roots -> formants (NaN-safe), sort, normalize ----
    float f[10];
#pragma unroll
    for (int i = 0; i < 10; i++) {
        float fr = atan2f(xi[i], xr[i]) * (10000.0f / (2.0f * (float)PI_D));
        bool valid = (xi[i] > 0.f) && (fr > 50.0f) && (fr < 4950.0f);
        f[i] = valid ? fr : 10000.0f;
    }
#pragma unroll
    for (int pass = 0; pass < 9; pass++) {
#pragma unroll
        for (int i = 0; i < 9; i++) {
            float lo = fminf(f[i], f[i + 1]);
            float hi = fmaxf(f[i], f[i + 1]);
            f[i] = lo; f[i + 1] = hi;
        }
    }

    float* ob = out + (size_t)b * (4 * T_DIM) + t;
#pragma unroll
    for (int q = 0; q < 4; q++)
        ob[q * T_DIM] = 2.0f * f[q] / 11025.0f - 1.0f;
}

extern "C" void kernel_launch(void* const* d_in, const int* in_sizes, int n_in,
                              void* d_out, int out_size) {
    const float* in = (const float*)d_in[0];
    float* out = (float*)d_out;
    (void)in_sizes; (void)n_in; (void)out_size;

    init_consts_kernel<<<1, 128>>>();
    formant_kernel<<<(NFRAMES + 127) / 128, 128>>>(in, out);
}

// round 5
// speedup vs baseline: 1.7146x; 1.7146x over previous
#include <cuda_runtime.h>
#include <math.h>

#define B_DIM 64
#define T_DIM 1000
#define P_ORD 10
#define NFRAMES (B_DIM * T_DIM)
#define PI_D 3.14159265358979323846

// Constant 11x11 map (double): r = M * c  (c = autocorrelation of predictor poly A)
// Folds:  S[k] = |rfft(A,512)[k]|^2 over 116 bins,  r = irfft(S, 230)[0:11]
__device__ double d_M[121];
__device__ float d_x0[20];

// Parallel init: one block per matrix entry (j,d); 114 threads split the k-sum.
__global__ void init_consts_kernel() {
    __shared__ double red[128];
    int e = blockIdx.x;
    int j = e / 11, d = e % 11;
    int k = threadIdx.x;

    double term = 0.0;
    if (k >= 1 && k <= 114) {
        double gd = (d == 0) ? 1.0 : 2.0 * cos(2.0 * PI_D * (double)k * (double)d / 512.0);
        term = 2.0 * gd * cos(2.0 * PI_D * (double)k * (double)j / 230.0);
    }
    red[threadIdx.x] = term;
    __syncthreads();
#pragma unroll
    for (int s = 64; s > 0; s >>= 1) {
        if (threadIdx.x < s) red[threadIdx.x] += red[threadIdx.x + s];
        __syncthreads();
    }
    if (threadIdx.x == 0) {
        double s = red[0];
        s += (d == 0) ? 1.0 : 2.0;                               // k = 0 bin
        double g115 = (d == 0) ? 1.0 : 2.0 * cos(2.0 * PI_D * 115.0 * (double)d / 512.0);
        s += ((j & 1) ? -1.0 : 1.0) * g115;                      // k = 115 Nyquist
        d_M[e] = s / 230.0;
    }
    if (e == 0 && threadIdx.x == 127) {
        double cr = 1.0, ci = 0.0;
        for (int p = 0; p < 10; p++) {
            double nr = cr * 0.4 - ci * 0.9;
            double ni = cr * 0.9 + ci * 0.4;
            cr = nr; ci = ni;
            d_x0[p]      = (float)nr;
            d_x0[10 + p] = (float)ni;
        }
    }
}

// Complex division matching XLA's lowering: Smith's algorithm (ratio form,
// branch on |c| >= |d|) with __divsc3-style NaN recovery. IEEE rn, no FMA.
__device__ __forceinline__ void cdivf(float a, float b, float c, float d,
                                      float& outr, float& outi) {
    float re, im;
    if (fabsf(c) >= fabsf(d)) {
        float r     = __fdiv_rn(d, c);
        float denom = __fadd_rn(c, __fmul_rn(d, r));
        re = __fdiv_rn(__fadd_rn(a, __fmul_rn(b, r)), denom);
        im = __fdiv_rn(__fsub_rn(b, __fmul_rn(a, r)), denom);
    } else {
        float r     = __fdiv_rn(c, d);
        float denom = __fadd_rn(__fmul_rn(c, r), d);
        re = __fdiv_rn(__fadd_rn(__fmul_rn(a, r), b), denom);
        im = __fdiv_rn(__fsub_rn(__fmul_rn(b, r), a), denom);
    }
    if (isnan(re) && isnan(im)) {
        if ((c == 0.0f && d == 0.0f) && (!isnan(a) || !isnan(b))) {
            re = copysignf(INFINITY, c) * a;
            im = copysignf(INFINITY, c) * b;
        } else if ((isinf(a) || isinf(b)) && isfinite(c) && isfinite(d)) {
            float aa = copysignf(isinf(a) ? 1.0f : 0.0f, a);
            float bb = copysignf(isinf(b) ? 1.0f : 0.0f, b);
            re = INFINITY * __fadd_rn(__fmul_rn(aa, c), __fmul_rn(bb, d));
            im = INFINITY * __fsub_rn(__fmul_rn(bb, c), __fmul_rn(aa, d));
        } else if ((isinf(c) || isinf(d)) && isfinite(a) && isfinite(b)) {
            float cc = copysignf(isinf(c) ? 1.0f : 0.0f, c);
            float dd = copysignf(isinf(d) ? 1.0f : 0.0f, d);
            re = 0.0f * __fadd_rn(__fmul_rn(a, cc), __fmul_rn(b, dd));
            im = 0.0f * __fsub_rn(__fmul_rn(b, cc), __fmul_rn(a, dd));
        }
    }
    outr = re; outi = im;
}

// Two threads per frame: even lane owns roots 0-4, odd lane roots 5-9.
__global__ void __launch_bounds__(128, 7)
formant_kernel(const float* __restrict__ in, float* __restrict__ out) {
    __shared__ double sM[121];
    __shared__ float sX0[20];
    if (threadIdx.x < 121) sM[threadIdx.x] = d_M[threadIdx.x];
    if (threadIdx.x < 20)  sX0[threadIdx.x] = d_x0[threadIdx.x];
    __syncthreads();

    const unsigned FULL = 0xffffffffu;
    int gtid  = blockIdx.x * 128 + threadIdx.x;
    int frame = gtid >> 1;
    int half  = gtid & 1;                 // 0: lo roots, 1: hi roots
    int b = frame / T_DIM;
    int t = frame - b * T_DIM;
    const float* base = in + (size_t)b * (P_ORD * T_DIM) + t;

    // ======== FRONT-END (fp64, even lane only) ========
    float pc[11];
#pragma unroll
    for (int i = 0; i < 11; i++) pc[i] = 0.f;

    if (half == 0) {
        double A[11];
        A[0] = 1.0;
        {
            double a[10];
            a[0] = (double)base[0];
#pragma unroll
            for (int p = 1; p < 10; p++) {
                double k = (double)base[p * T_DIM];
                double na[10];
#pragma unroll
                for (int i = 0; i < p; i++) na[i] = a[i] + k * a[p - 1 - i];
#pragma unroll
                for (int i = 0; i < p; i++) a[i] = na[i];
                a[p] = k;
            }
#pragma unroll
            for (int i = 0; i < 10; i++) A[i + 1] = a[i];
        }

        double c[11];
#pragma unroll
        for (int d = 0; d < 11; d++) {
            double s = 0.0;
#pragma unroll
            for (int n = 0; n < 11 - d; n++) s = fma(A[n], A[n + d], s);
            c[d] = s;
        }

        double r[11];
#pragma unroll
        for (int j = 0; j < 11; j++) {
            double s = 0.0;
#pragma unroll
            for (int d = 0; d < 11; d++) s = fma(sM[j * 11 + d], c[d], s);
            r[j] = s;
        }

        pc[0] = 1.0f;
        {
            double a[10];
            double k0 = -r[1] / r[0];
            a[0] = k0;
            double err = r[0] * (1.0 - k0 * k0);
#pragma unroll
            for (int m = 1; m < 10; m++) {
                double acc = r[m + 1];
#pragma unroll
                for (int i = 0; i < m; i++) acc = fma(a[i], r[m - i], acc);
                double k = -acc / err;
                double na[10];
#pragma unroll
                for (int i = 0; i < m; i++) na[i] = a[i] + k * a[m - 1 - i];
#pragma unroll
                for (int i = 0; i < m; i++) a[i] = na[i];
                a[m] = k;
                err *= (1.0 - k * k);
            }
#pragma unroll
            for (int i = 0; i < 10; i++) pc[i + 1] = (float)a[i];
        }
    }
    // broadcast pc from even lane to its odd partner
#pragma unroll
    for (int i = 0; i < 11; i++) {
        float v = __shfl_xor_sync(FULL, pc[i], 1);
        if (half) pc[i] = v;
    }

    // ======== DURAND-KERNER: 5 roots per thread, XLA-faithful fp32 ========
    float xr[5], xi[5];
#pragma unroll
    for (int i = 0; i < 5; i++) {
        xr[i] = sX0[half * 5 + i];
        xi[i] = sX0[10 + half * 5 + i];
    }

#pragma unroll 1
    for (int it = 0; it < 30; it++) {
        // fetch partner's current roots
        float pr[5], pimg[5];
#pragma unroll
        for (int j = 0; j < 5; j++) {
            pr[j]   = __shfl_xor_sync(FULL, xr[j], 1);
            pimg[j] = __shfl_xor_sync(FULL, xi[j], 1);
        }
        // global-ordered halves: lo = roots 0-4, hi = roots 5-9
        float loR[5], loI[5], hiR[5], hiI[5];
#pragma unroll
        for (int j = 0; j < 5; j++) {
            loR[j] = half ? pr[j]   : xr[j];
            loI[j] = half ? pimg[j] : xi[j];
            hiR[j] = half ? xr[j]   : pr[j];
            hiI[j] = half ? xi[j]   : pimg[j];
        }

        float nxr[5], nxi[5];
#pragma unroll
        for (int i = 0; i < 5; i++) {
            float X = xr[i], Y = xi[i];
            // Horner polyval (sequential, unfused)
            float yr = pc[0], yi = 0.f;
#pragma unroll
            for (int m = 1; m <= 10; m++) {
                float tr = __fadd_rn(__fsub_rn(__fmul_rn(yr, X), __fmul_rn(yi, Y)), pc[m]);
                float ti = __fadd_rn(__fmul_rn(yr, Y), __fmul_rn(yi, X));
                yr = tr; yi = ti;
            }
            // prod over j = 0..9 in global order (eye adds 1 at j == my global index)
            float dr = 1.f, di = 0.f;
#pragma unroll
            for (int j = 0; j < 5; j++) {
                float eye = (half == 0 && i == j) ? 1.f : 0.f;
                float er = __fadd_rn(__fsub_rn(X, loR[j]), eye);
                float ei = __fsub_rn(Y, loI[j]);
                float tr = __fsub_rn(__fmul_rn(dr, er), __fmul_rn(di, ei));
                float ti = __fadd_rn(__fmul_rn(dr, ei), __fmul_rn(di, er));
                dr = tr; di = ti;
            }
#pragma unroll
            for (int j = 0; j < 5; j++) {
                float eye = (half == 1 && i == j) ? 1.f : 0.f;
                float er = __fadd_rn(__fsub_rn(X, hiR[j]), eye);
                float ei = __fsub_rn(Y, hiI[j]);
                float tr = __fsub_rn(__fmul_rn(dr, er), __fmul_rn(di, ei));
                float ti = __fadd_rn(__fmul_rn(dr, ei), __fmul_rn(di, er));
                dr = tr; di = ti;
            }
            dr = __fadd_rn(dr, 1e-12f);
            float qr, qi;
            cdivf(yr, yi, dr, di, qr, qi);
            nxr[i] = __fsub_rn(X, qr);
            nxi[i] = __fsub_rn(Y, qi);
        }
#pragma unroll
        for (int i = 0; i < 5; i++) { xr[i] = nxr[i]; xi[i] = nxi[i]; }
    }

    // ======== roots -> formants, exchange, sort, write (even lane) ========
    float f5[5];
#pragma unroll
    for (int i = 0; i < 5; i++) {
        float fr = atan2f(xi[i], xr[i]) * (10000.0f / (2.0f * (float)PI_D));
        bool valid = (xi[i] > 0.f) && (fr > 50.0f) && (fr < 4950.0f);
        f5[i] = valid ? fr : 10000.0f;
    }
    float pf[5];
#pragma unroll
    for (int j = 0; j < 5; j++) pf[j] = __shfl_xor_sync(FULL, f5[j], 1);

    float f[10];
#pragma unroll
    for (int j = 0; j < 5; j++) {
        f[j]     = half ? pf[j] : f5[j];
        f[5 + j] = half ? f5[j] : pf[j];
    }
#pragma unroll
    for (int pass = 0; pass < 9; pass++) {
#pragma unroll
        for (int i = 0; i < 9; i++) {
            float lo = fminf(f[i], f[i + 1]);
            float hi = fmaxf(f[i], f[i + 1]);
            f[i] = lo; f[i + 1] = hi;
        }
    }

    if (half == 0) {
        float* ob = out + (size_t)b * (4 * T_DIM) + t;
#pragma unroll
        for (int q = 0; q < 4; q++)
            ob[q * T_DIM] = 2.0f * f[q] / 11025.0f - 1.0f;
    }
}

extern "C" void kernel_launch(void* const* d_in, const int* in_sizes, int n_in,
                              void* d_out, int out_size) {
    const float* in = (const float*)d_in[0];
    float* out = (float*)d_out;
    (void)in_sizes; (void)n_in; (void)out_size;

    init_consts_kernel<<<121, 128>>>();
    formant_kernel<<<(NFRAMES * 2) / 128, 128>>>(in, out);
}